// round 3
// baseline (speedup 1.0000x reference)
#include <cuda_runtime.h>
#include <cstdint>

// ============================================================================
// UniversalKANLinear: out[b,o] = sum_k (softplus(x[b,k])-ln2) * W[o,k]
//                              + (softplus(1)-ln2) * W[o,2048]
// B=8192, K=2048, N=2048.
// Toolchain targets plain sm_103 (no tcgen05/TMA). Strategy:
//   1) prep: phi(x) and W repack, pre-rounded to tf32 (RNA) so mma.sync's
//      truncation is exact.
//   2) GEMM: mma.sync.m16n8k8.tf32, CTA tile 128x256x32, 8 warps (64x64 each),
//      3-stage cp.async pipeline, fused bias epilogue.
// ============================================================================

#define BATCH_M 8192
#define DIM_K   2048
#define DIM_N   2048
#define W_COLS  2049

#define BM 128
#define BN 256
#define BK 32
#define STAGES 3
#define KITERS (DIM_K / BK)     // 64

#define LDT 36                              // BK + 4 pad (floats); 144B rows (16B-aligned)
#define A_STAGE_FLOATS (BM * LDT)           // 4608
#define B_STAGE_FLOATS (BN * LDT)           // 9216
#define STAGE_FLOATS   (A_STAGE_FLOATS + B_STAGE_FLOATS)  // 13824
#define SMEM_BYTES     (STAGES * STAGE_FLOATS * 4)        // 165888

#define C_BIAS 0.62011450695827751f   // softplus(1) - ln2
#define LN2F   0.69314718055994531f

// ---------------- scratch (device globals: allocation-free rule) -----------
__device__ __align__(1024) float g_A[(size_t)BATCH_M * DIM_K];  // phi(x), tf32-rounded
__device__ __align__(1024) float g_B[(size_t)DIM_N * DIM_K];    // W repack, tf32-rounded
__device__ __align__(128)  float g_bias[DIM_N];

// ---------------- helpers ---------------------------------------------------
__device__ __forceinline__ uint32_t smem_u32(const void* p) {
    uint32_t a;
    asm("{ .reg .u64 t; cvta.to.shared.u64 t, %1; cvt.u32.u64 %0, t; }" : "=r"(a) : "l"(p));
    return a;
}

#define CP_ASYNC16(dst_u32, src_ptr) \
    asm volatile("cp.async.cg.shared.global [%0], [%1], 16;" \
                 :: "r"(dst_u32), "l"(src_ptr) : "memory")
#define CP_COMMIT() asm volatile("cp.async.commit_group;" ::: "memory")
#define CP_WAIT(N)  asm volatile("cp.async.wait_group %0;" :: "n"(N) : "memory")

#define MMA_TF32(c, a, b) \
    asm volatile("mma.sync.aligned.m16n8k8.row.col.f32.tf32.tf32.f32 " \
                 "{%0,%1,%2,%3}, {%4,%5,%6,%7}, {%8,%9}, {%0,%1,%2,%3};" \
                 : "+f"((c)[0]), "+f"((c)[1]), "+f"((c)[2]), "+f"((c)[3]) \
                 : "r"((a)[0]), "r"((a)[1]), "r"((a)[2]), "r"((a)[3]), \
                   "r"((b)[0]), "r"((b)[1]))

// ---------------- pre-pass kernels -----------------------------------------
__device__ __forceinline__ float phi_tf32(float x) {
    float sp = fmaxf(x, 0.0f) + log1pf(__expf(-fabsf(x)));
    float r = sp - LN2F;
    asm("cvt.rna.tf32.f32 %0, %0;" : "+f"(r));
    return r;
}

__global__ void prep_x_kernel(const float* __restrict__ x) {
    size_t i = (size_t)blockIdx.x * blockDim.x + threadIdx.x;  // over float4s
    float4 v = reinterpret_cast<const float4*>(x)[i];
    v.x = phi_tf32(v.x);
    v.y = phi_tf32(v.y);
    v.z = phi_tf32(v.z);
    v.w = phi_tf32(v.w);
    reinterpret_cast<float4*>(g_A)[i] = v;
}

__global__ void prep_w_kernel(const float* __restrict__ W) {
    size_t idx = (size_t)blockIdx.x * blockDim.x + threadIdx.x;  // DIM_N*DIM_K scalars
    int o = (int)(idx >> 11);
    int k = (int)(idx & 2047);
    float v = W[(size_t)o * W_COLS + k];
    asm("cvt.rna.tf32.f32 %0, %0;" : "+f"(v));
    g_B[idx] = v;
    if (idx < DIM_N) {
        g_bias[idx] = C_BIAS * W[idx * W_COLS + (W_COLS - 1)];
    }
}

// ---------------- GEMM kernel ----------------------------------------------
__global__ void __launch_bounds__(256, 1)
kan_gemm_kernel(float* __restrict__ out) {
    extern __shared__ float smem[];
    const uint32_t sbase = smem_u32(smem);
    const int tid = threadIdx.x;
    const int lane = tid & 31;
    const int wid = tid >> 5;
    const int wm = wid & 1;        // 2 warp rows (64 each) over BM=128
    const int wn = wid >> 1;       // 4 warp cols (64 each) over BN=256
    const int m0 = blockIdx.x * BM;
    const int n0 = blockIdx.y * BN;
    const int r = lane >> 2;       // 0..7
    const int c = lane & 3;        // 0..3

    // ---- stage copy: A tile (128x32) + B tile (256x32), 16B cp.async ----
    auto copy_stage = [&](int s, int kt) {
        const uint32_t sA = sbase + (uint32_t)s * (STAGE_FLOATS * 4);
        const uint32_t sB = sA + A_STAGE_FLOATS * 4;
        const float* gA = g_A + (size_t)m0 * DIM_K + (size_t)kt * BK;
        const float* gB = g_B + (size_t)n0 * DIM_K + (size_t)kt * BK;
        #pragma unroll
        for (int i = 0; i < 4; i++) {            // A: 1024 float4s
            int v = tid + i * 256;
            int row = v >> 3, kc = v & 7;
            CP_ASYNC16(sA + row * (LDT * 4) + kc * 16,
                       gA + (size_t)row * DIM_K + kc * 4);
        }
        #pragma unroll
        for (int i = 0; i < 8; i++) {            // B: 2048 float4s
            int v = tid + i * 256;
            int row = v >> 3, kc = v & 7;
            CP_ASYNC16(sB + row * (LDT * 4) + kc * 16,
                       gB + (size_t)row * DIM_K + kc * 4);
        }
    };

    float acc[4][8][4];
    #pragma unroll
    for (int mt = 0; mt < 4; mt++)
        #pragma unroll
        for (int nt = 0; nt < 8; nt++)
            #pragma unroll
            for (int i = 0; i < 4; i++) acc[mt][nt][i] = 0.0f;

    copy_stage(0, 0); CP_COMMIT();
    copy_stage(1, 1); CP_COMMIT();

    int rs = 0;  // read stage
    for (int kt = 0; kt < KITERS; kt++) {
        CP_WAIT(1);
        __syncthreads();

        const float* As = smem + rs * STAGE_FLOATS + (wm * 64) * LDT;
        const float* Bs = smem + rs * STAGE_FLOATS + A_STAGE_FLOATS + (wn * 64) * LDT;

        #pragma unroll
        for (int ks = 0; ks < 4; ks++) {        // 4 x k8 steps over BK=32
            uint32_t a[4][4], b[8][2];
            #pragma unroll
            for (int mt = 0; mt < 4; mt++) {
                const float* ap = As + (mt * 16 + r) * LDT + ks * 8 + c;
                a[mt][0] = __float_as_uint(ap[0]);
                a[mt][1] = __float_as_uint(ap[8 * LDT]);
                a[mt][2] = __float_as_uint(ap[4]);
                a[mt][3] = __float_as_uint(ap[8 * LDT + 4]);
            }
            #pragma unroll
            for (int nt = 0; nt < 8; nt++) {
                const float* bp = Bs + (nt * 8 + r) * LDT + ks * 8 + c;
                b[nt][0] = __float_as_uint(bp[0]);
                b[nt][1] = __float_as_uint(bp[4]);
            }
            #pragma unroll
            for (int mt = 0; mt < 4; mt++)
                #pragma unroll
                for (int nt = 0; nt < 8; nt++)
                    MMA_TF32(acc[mt][nt], a[mt], b[nt]);
        }

        // issue copy for kt+2 into the stage just freed (barrier at loop top
        // of this iteration guarantees all warps finished reading it)
        if (kt + 2 < KITERS) copy_stage((kt + 2) % STAGES, kt + 2);
        CP_COMMIT();
        if (++rs == STAGES) rs = 0;
    }

    // ---- epilogue: acc + bias -> out ----
    const int mbase = m0 + wm * 64;
    const int nbase = n0 + wn * 64;
    #pragma unroll
    for (int mt = 0; mt < 4; mt++) {
        #pragma unroll
        for (int nt = 0; nt < 8; nt++) {
            int mrow = mbase + mt * 16 + r;
            int ncol = nbase + nt * 8 + 2 * c;
            float2 bv = *reinterpret_cast<const float2*>(g_bias + ncol);
            float2 v0, v1;
            v0.x = acc[mt][nt][0] + bv.x;
            v0.y = acc[mt][nt][1] + bv.y;
            v1.x = acc[mt][nt][2] + bv.x;
            v1.y = acc[mt][nt][3] + bv.y;
            *reinterpret_cast<float2*>(out + (size_t)mrow * DIM_N + ncol) = v0;
            *reinterpret_cast<float2*>(out + (size_t)(mrow + 8) * DIM_N + ncol) = v1;
        }
    }
}

// ---------------- host launch ----------------------------------------------
extern "C" void kernel_launch(void* const* d_in, const int* in_sizes, int n_in,
                              void* d_out, int out_size) {
    const float* x = (const float*)d_in[0];
    const float* W = (const float*)d_in[1];
    float* out = (float*)d_out;

    cudaFuncSetAttribute(kan_gemm_kernel, cudaFuncAttributeMaxDynamicSharedMemorySize,
                         SMEM_BYTES);

    // phi(x) -> g_A (tf32-rounded)
    prep_x_kernel<<<(BATCH_M * DIM_K / 4) / 256, 256>>>(x);
    // W repack -> g_B (tf32-rounded) + bias
    prep_w_kernel<<<(DIM_N * DIM_K) / 1024, 1024>>>(W);
    // GEMM
    kan_gemm_kernel<<<dim3(BATCH_M / BM, DIM_N / BN), 256, SMEM_BYTES>>>(out);
}

// round 4
// speedup vs baseline: 1.3916x; 1.3916x over previous
#include <cuda_runtime.h>
#include <cuda_fp16.h>
#include <cstdint>

// ============================================================================
// UniversalKANLinear: out[b,o] = sum_k (softplus(x[b,k])-ln2) * W[o,k]
//                              + (softplus(1)-ln2) * W[o,2048]
// B=8192, K=2048, N=2048.
// sm_103 (no tcgen05/TMA). fp16 mma.sync.m16n8k16 (same 11-bit mantissa as
// tf32, 2x K per instruction on the legacy HMMA pipe), fp32 accumulate.
//   1) prep: phi(x) -> fp16, W -> fp16, bias (fp32).
//   2) GEMM: CTA 128x256x64, 8 warps (64x64), 4-stage cp.async, SW128
//      XOR-swizzled smem, ldmatrix.x4 operand loads, fused bias epilogue.
// ============================================================================

#define BATCH_M 8192
#define DIM_K   2048
#define DIM_N   2048
#define W_COLS  2049

#define BM 128
#define BN 256
#define BK 64
#define STAGES 4
#define KITERS (DIM_K / BK)     // 32

// smem: rows of 64 fp16 = 128 B, XOR-swizzled in 16B chunks
#define A_STAGE_BYTES (BM * 128)                 // 16384
#define B_STAGE_BYTES (BN * 128)                 // 32768
#define STAGE_BYTES   (A_STAGE_BYTES + B_STAGE_BYTES)  // 49152
#define SMEM_BYTES    (STAGES * STAGE_BYTES)           // 196608

#define C_BIAS 0.62011450695827751f   // softplus(1) - ln2
#define LN2F   0.69314718055994531f

// ---------------- scratch (device globals: allocation-free rule) -----------
__device__ __align__(1024) __half g_A[(size_t)BATCH_M * DIM_K];  // 32 MB phi(x)
__device__ __align__(1024) __half g_B[(size_t)DIM_N * DIM_K];    // 8 MB W
__device__ __align__(128)  float  g_bias[DIM_N];

// ---------------- helpers ---------------------------------------------------
__device__ __forceinline__ uint32_t smem_u32(const void* p) {
    uint32_t a;
    asm("{ .reg .u64 t; cvta.to.shared.u64 t, %1; cvt.u32.u64 %0, t; }" : "=r"(a) : "l"(p));
    return a;
}

#define CP_ASYNC16(dst_u32, src_ptr) \
    asm volatile("cp.async.cg.shared.global [%0], [%1], 16;" \
                 :: "r"(dst_u32), "l"(src_ptr) : "memory")
#define CP_COMMIT() asm volatile("cp.async.commit_group;" ::: "memory")
#define CP_WAIT(N)  asm volatile("cp.async.wait_group %0;" :: "n"(N) : "memory")

#define LDMATRIX_X4(r0, r1, r2, r3, addr) \
    asm volatile("ldmatrix.sync.aligned.m8n8.x4.shared.b16 {%0,%1,%2,%3}, [%4];" \
                 : "=r"(r0), "=r"(r1), "=r"(r2), "=r"(r3) : "r"(addr))

#define MMA_F16(c, a0, a1, a2, a3, b0, b1) \
    asm volatile("mma.sync.aligned.m16n8k16.row.col.f32.f16.f16.f32 " \
                 "{%0,%1,%2,%3}, {%4,%5,%6,%7}, {%8,%9}, {%0,%1,%2,%3};" \
                 : "+f"((c)[0]), "+f"((c)[1]), "+f"((c)[2]), "+f"((c)[3]) \
                 : "r"(a0), "r"(a1), "r"(a2), "r"(a3), "r"(b0), "r"(b1))

// ---------------- pre-pass kernels -----------------------------------------
__device__ __forceinline__ float phi_f(float x) {
    // softplus(x) - ln2, fast path: max(x,0) + log(1 + exp(-|x|)) - ln2
    float t = __expf(-fabsf(x));
    return fmaxf(x, 0.0f) + __logf(1.0f + t) - LN2F;
}

__global__ void prep_x_kernel(const float* __restrict__ x) {
    size_t i = (size_t)blockIdx.x * blockDim.x + threadIdx.x;  // over float4s
    float4 v = reinterpret_cast<const float4*>(x)[i];
    __half2 h0 = __floats2half2_rn(phi_f(v.x), phi_f(v.y));
    __half2 h1 = __floats2half2_rn(phi_f(v.z), phi_f(v.w));
    uint2 pack;
    pack.x = *reinterpret_cast<uint32_t*>(&h0);
    pack.y = *reinterpret_cast<uint32_t*>(&h1);
    reinterpret_cast<uint2*>(g_A)[i] = pack;
}

__global__ void prep_w_kernel(const float* __restrict__ W) {
    size_t idx = (size_t)blockIdx.x * blockDim.x + threadIdx.x;  // DIM_N*DIM_K
    int o = (int)(idx >> 11);
    int k = (int)(idx & 2047);
    g_B[idx] = __float2half_rn(W[(size_t)o * W_COLS + k]);
    if (idx < DIM_N) {
        g_bias[idx] = C_BIAS * W[idx * W_COLS + (W_COLS - 1)];
    }
}

// ---------------- GEMM kernel ----------------------------------------------
// smem addr for (row, 16B-chunk c16): row*128 + (c16 ^ (row&7))*16
__global__ void __launch_bounds__(256, 1)
kan_gemm_kernel(float* __restrict__ out) {
    extern __shared__ char smem[];
    const uint32_t sbase = smem_u32(smem);
    const int tid = threadIdx.x;
    const int lane = tid & 31;
    const int wid = tid >> 5;
    const int wm = wid & 1;        // 2 warp rows over BM=128 (64 each)
    const int wn = wid >> 1;       // 4 warp cols over BN=256 (64 each)
    const int m0 = blockIdx.x * BM;
    const int n0 = blockIdx.y * BN;
    const int r = lane >> 2;       // 0..7
    const int c = lane & 3;        // 0..3

    // ---- stage copy: A tile (128 rows x 128B) + B tile (256 rows x 128B) ----
    auto copy_stage = [&](int s, int kt) {
        const uint32_t sA = sbase + (uint32_t)s * STAGE_BYTES;
        const uint32_t sB = sA + A_STAGE_BYTES;
        const __half* gA = g_A + (size_t)m0 * DIM_K + (size_t)kt * BK;
        const __half* gB = g_B + (size_t)n0 * DIM_K + (size_t)kt * BK;
        #pragma unroll
        for (int i = 0; i < 4; i++) {            // A: 1024 16B chunks
            int v = tid + i * 256;
            int row = v >> 3, c16 = v & 7;
            CP_ASYNC16(sA + row * 128 + ((c16 ^ (row & 7)) * 16),
                       gA + (size_t)row * DIM_K + c16 * 8);
        }
        #pragma unroll
        for (int i = 0; i < 8; i++) {            // B: 2048 16B chunks
            int v = tid + i * 256;
            int row = v >> 3, c16 = v & 7;
            CP_ASYNC16(sB + row * 128 + ((c16 ^ (row & 7)) * 16),
                       gB + (size_t)row * DIM_K + c16 * 8);
        }
    };

    float acc[4][8][4];
    #pragma unroll
    for (int mt = 0; mt < 4; mt++)
        #pragma unroll
        for (int nt = 0; nt < 8; nt++)
            #pragma unroll
            for (int i = 0; i < 4; i++) acc[mt][nt][i] = 0.0f;

    copy_stage(0, 0); CP_COMMIT();
    copy_stage(1, 1); CP_COMMIT();
    copy_stage(2, 2); CP_COMMIT();

    // ldmatrix lane roles (precomputed, loop-invariant)
    const int a_row = (lane & 15);           // lanes 0-15: rows 0-15 of 16-row tile
    const int a_ch  = (lane >> 4);           // 0: k 0-7, 1: k 8-15 (16B chunks)
    const int b_nrow = ((lane >> 4) << 3) + (lane & 7);  // 0-7 then 8-15
    const int b_ch  = (lane >> 3) & 1;       // k-chunk within k16

    int rs = 0;  // read stage
    for (int kt = 0; kt < KITERS; kt++) {
        CP_WAIT(2);
        __syncthreads();
        if (kt + 3 < KITERS) copy_stage((kt + 3) & 3, kt + 3);
        CP_COMMIT();

        const uint32_t sA = sbase + (uint32_t)rs * STAGE_BYTES + (wm * 64) * 128;
        const uint32_t sB = sbase + (uint32_t)rs * STAGE_BYTES + A_STAGE_BYTES
                            + (wn * 64) * 128;

        #pragma unroll
        for (int ks = 0; ks < 4; ks++) {        // 4 x k16 steps over BK=64
            uint32_t a[4][4], b[4][4];
            #pragma unroll
            for (int mt = 0; mt < 4; mt++) {
                int row = mt * 16 + a_row;
                int ch = ks * 2 + a_ch;
                uint32_t addr = sA + row * 128 + ((ch ^ (row & 7)) * 16);
                LDMATRIX_X4(a[mt][0], a[mt][1], a[mt][2], a[mt][3], addr);
            }
            #pragma unroll
            for (int np = 0; np < 4; np++) {    // pairs of n-tiles (16 n rows)
                int row = np * 16 + b_nrow;
                int ch = ks * 2 + b_ch;
                uint32_t addr = sB + row * 128 + ((ch ^ (row & 7)) * 16);
                LDMATRIX_X4(b[np][0], b[np][1], b[np][2], b[np][3], addr);
            }
            #pragma unroll
            for (int mt = 0; mt < 4; mt++) {
                #pragma unroll
                for (int np = 0; np < 4; np++) {
                    MMA_F16(acc[mt][2 * np],     a[mt][0], a[mt][1], a[mt][2], a[mt][3],
                            b[np][0], b[np][1]);
                    MMA_F16(acc[mt][2 * np + 1], a[mt][0], a[mt][1], a[mt][2], a[mt][3],
                            b[np][2], b[np][3]);
                }
            }
        }
        if (++rs == STAGES) rs = 0;
    }

    // ---- epilogue: acc + bias -> out ----
    const int mbase = m0 + wm * 64;
    const int nbase = n0 + wn * 64;
    #pragma unroll
    for (int mt = 0; mt < 4; mt++) {
        #pragma unroll
        for (int nt = 0; nt < 8; nt++) {
            int mrow = mbase + mt * 16 + r;
            int ncol = nbase + nt * 8 + 2 * c;
            float2 bv = *reinterpret_cast<const float2*>(g_bias + ncol);
            float2 v0, v1;
            v0.x = acc[mt][nt][0] + bv.x;
            v0.y = acc[mt][nt][1] + bv.y;
            v1.x = acc[mt][nt][2] + bv.x;
            v1.y = acc[mt][nt][3] + bv.y;
            *reinterpret_cast<float2*>(out + (size_t)mrow * DIM_N + ncol) = v0;
            *reinterpret_cast<float2*>(out + (size_t)(mrow + 8) * DIM_N + ncol) = v1;
        }
    }
}

// ---------------- host launch ----------------------------------------------
extern "C" void kernel_launch(void* const* d_in, const int* in_sizes, int n_in,
                              void* d_out, int out_size) {
    const float* x = (const float*)d_in[0];
    const float* W = (const float*)d_in[1];
    float* out = (float*)d_out;

    cudaFuncSetAttribute(kan_gemm_kernel, cudaFuncAttributeMaxDynamicSharedMemorySize,
                         SMEM_BYTES);

    prep_x_kernel<<<(BATCH_M * DIM_K / 4) / 256, 256>>>(x);
    prep_w_kernel<<<(DIM_N * DIM_K) / 1024, 1024>>>(W);
    kan_gemm_kernel<<<dim3(BATCH_M / BM, DIM_N / BN), 256, SMEM_BYTES>>>(out);
}

// round 5
// speedup vs baseline: 2.4695x; 1.7746x over previous
#include <cuda_runtime.h>
#include <cuda_fp16.h>
#include <cstdint>

// ============================================================================
// UniversalKANLinear: out[b,o] = sum_k (softplus(x[b,k])-ln2) * W[o,k]
//                              + (softplus(1)-ln2) * W[o,2048]
// B=8192, K=2048, N=2048.
// sm_103 (no tcgen05/TMA). fp16 mma.sync.m16n8k16, fp32 accumulate.
// R5: CTA tile 128x128x64 (was 128x256): 96KB smem -> 2 CTAs/SM, 1024 CTAs
//     -> wave-quantization loss ~15.6% -> ~1%. Warp tile 64x32.
// ============================================================================

#define BATCH_M 8192
#define DIM_K   2048
#define DIM_N   2048
#define W_COLS  2049

#define BM 128
#define BN 128
#define BK 64
#define STAGES 3
#define KITERS (DIM_K / BK)     // 32

// smem: rows of 64 fp16 = 128 B, XOR-swizzled in 16B chunks
#define A_STAGE_BYTES (BM * 128)                 // 16384
#define B_STAGE_BYTES (BN * 128)                 // 16384
#define STAGE_BYTES   (A_STAGE_BYTES + B_STAGE_BYTES)  // 32768
#define SMEM_BYTES    (STAGES * STAGE_BYTES)           // 98304

#define C_BIAS 0.62011450695827751f   // softplus(1) - ln2
#define LN2F   0.69314718055994531f

// ---------------- scratch (device globals: allocation-free rule) -----------
__device__ __align__(1024) __half g_A[(size_t)BATCH_M * DIM_K];  // 32 MB phi(x)
__device__ __align__(1024) __half g_B[(size_t)DIM_N * DIM_K];    // 8 MB W
__device__ __align__(128)  float  g_bias[DIM_N];

// ---------------- helpers ---------------------------------------------------
__device__ __forceinline__ uint32_t smem_u32(const void* p) {
    uint32_t a;
    asm("{ .reg .u64 t; cvta.to.shared.u64 t, %1; cvt.u32.u64 %0, t; }" : "=r"(a) : "l"(p));
    return a;
}

#define CP_ASYNC16(dst_u32, src_ptr) \
    asm volatile("cp.async.cg.shared.global [%0], [%1], 16;" \
                 :: "r"(dst_u32), "l"(src_ptr) : "memory")
#define CP_COMMIT() asm volatile("cp.async.commit_group;" ::: "memory")
#define CP_WAIT(N)  asm volatile("cp.async.wait_group %0;" :: "n"(N) : "memory")

#define LDMATRIX_X4(r0, r1, r2, r3, addr) \
    asm volatile("ldmatrix.sync.aligned.m8n8.x4.shared.b16 {%0,%1,%2,%3}, [%4];" \
                 : "=r"(r0), "=r"(r1), "=r"(r2), "=r"(r3) : "r"(addr))

#define MMA_F16(c, a0, a1, a2, a3, b0, b1) \
    asm volatile("mma.sync.aligned.m16n8k16.row.col.f32.f16.f16.f32 " \
                 "{%0,%1,%2,%3}, {%4,%5,%6,%7}, {%8,%9}, {%0,%1,%2,%3};" \
                 : "+f"((c)[0]), "+f"((c)[1]), "+f"((c)[2]), "+f"((c)[3]) \
                 : "r"(a0), "r"(a1), "r"(a2), "r"(a3), "r"(b0), "r"(b1))

// ---------------- pre-pass kernels -----------------------------------------
__device__ __forceinline__ float phi_f(float x) {
    float t = __expf(-fabsf(x));
    return fmaxf(x, 0.0f) + __logf(1.0f + t) - LN2F;
}

__global__ void prep_x_kernel(const float* __restrict__ x) {
    size_t i = (size_t)blockIdx.x * blockDim.x + threadIdx.x;  // over float4s
    float4 v = reinterpret_cast<const float4*>(x)[i];
    __half2 h0 = __floats2half2_rn(phi_f(v.x), phi_f(v.y));
    __half2 h1 = __floats2half2_rn(phi_f(v.z), phi_f(v.w));
    uint2 pack;
    pack.x = *reinterpret_cast<uint32_t*>(&h0);
    pack.y = *reinterpret_cast<uint32_t*>(&h1);
    reinterpret_cast<uint2*>(g_A)[i] = pack;
}

__global__ void prep_w_kernel(const float* __restrict__ W) {
    size_t idx = (size_t)blockIdx.x * blockDim.x + threadIdx.x;  // DIM_N*DIM_K
    int o = (int)(idx >> 11);
    int k = (int)(idx & 2047);
    g_B[idx] = __float2half_rn(W[(size_t)o * W_COLS + k]);
    if (idx < DIM_N) {
        g_bias[idx] = C_BIAS * W[idx * W_COLS + (W_COLS - 1)];
    }
}

// ---------------- GEMM kernel ----------------------------------------------
// smem addr for (row, 16B-chunk c16): row*128 + (c16 ^ (row&7))*16
__global__ void __launch_bounds__(256, 2)
kan_gemm_kernel(float* __restrict__ out) {
    extern __shared__ char smem[];
    const uint32_t sbase = smem_u32(smem);
    const int tid = threadIdx.x;
    const int lane = tid & 31;
    const int wid = tid >> 5;
    const int wm = wid & 1;        // 2 warp rows over BM=128 (64 each)
    const int wn = wid >> 1;       // 4 warp cols over BN=128 (32 each)
    const int m0 = blockIdx.x * BM;
    const int n0 = blockIdx.y * BN;
    const int r = lane >> 2;       // 0..7
    const int c = lane & 3;        // 0..3

    // ---- stage copy: A tile (128 rows x 128B) + B tile (128 rows x 128B) ----
    auto copy_stage = [&](int s, int kt) {
        const uint32_t sA = sbase + (uint32_t)s * STAGE_BYTES;
        const uint32_t sB = sA + A_STAGE_BYTES;
        const __half* gA = g_A + (size_t)m0 * DIM_K + (size_t)kt * BK;
        const __half* gB = g_B + (size_t)n0 * DIM_K + (size_t)kt * BK;
        #pragma unroll
        for (int i = 0; i < 4; i++) {            // A: 1024 16B chunks
            int v = tid + i * 256;
            int row = v >> 3, c16 = v & 7;
            CP_ASYNC16(sA + row * 128 + ((c16 ^ (row & 7)) * 16),
                       gA + (size_t)row * DIM_K + c16 * 8);
        }
        #pragma unroll
        for (int i = 0; i < 4; i++) {            // B: 1024 16B chunks
            int v = tid + i * 256;
            int row = v >> 3, c16 = v & 7;
            CP_ASYNC16(sB + row * 128 + ((c16 ^ (row & 7)) * 16),
                       gB + (size_t)row * DIM_K + c16 * 8);
        }
    };

    float acc[4][4][4];
    #pragma unroll
    for (int mt = 0; mt < 4; mt++)
        #pragma unroll
        for (int nt = 0; nt < 4; nt++)
            #pragma unroll
            for (int i = 0; i < 4; i++) acc[mt][nt][i] = 0.0f;

    copy_stage(0, 0); CP_COMMIT();
    copy_stage(1, 1); CP_COMMIT();

    // ldmatrix lane roles (loop-invariant)
    const int a_row = (lane & 15);                       // row within 16-row tile
    const int a_ch  = (lane >> 4);                       // k16 half (16B chunk)
    const int b_nrow = ((lane >> 4) << 3) + (lane & 7);  // 0-7 then 8-15
    const int b_ch  = (lane >> 3) & 1;                   // k-chunk within k16

    int rs = 0;  // read stage
    for (int kt = 0; kt < KITERS; kt++) {
        CP_WAIT(1);
        __syncthreads();
        if (kt + 2 < KITERS) copy_stage((kt + 2) % STAGES, kt + 2);
        CP_COMMIT();

        const uint32_t sA = sbase + (uint32_t)rs * STAGE_BYTES + (wm * 64) * 128;
        const uint32_t sB = sbase + (uint32_t)rs * STAGE_BYTES + A_STAGE_BYTES
                            + (wn * 32) * 128;

        #pragma unroll
        for (int ks = 0; ks < 4; ks++) {        // 4 x k16 steps over BK=64
            uint32_t a[4][4], b[2][4];
            #pragma unroll
            for (int mt = 0; mt < 4; mt++) {
                int row = mt * 16 + a_row;
                int ch = ks * 2 + a_ch;
                uint32_t addr = sA + row * 128 + ((ch ^ (row & 7)) * 16);
                LDMATRIX_X4(a[mt][0], a[mt][1], a[mt][2], a[mt][3], addr);
            }
            #pragma unroll
            for (int np = 0; np < 2; np++) {    // 2 x 16 n-rows = 32 cols
                int row = np * 16 + b_nrow;
                int ch = ks * 2 + b_ch;
                uint32_t addr = sB + row * 128 + ((ch ^ (row & 7)) * 16);
                LDMATRIX_X4(b[np][0], b[np][1], b[np][2], b[np][3], addr);
            }
            #pragma unroll
            for (int mt = 0; mt < 4; mt++) {
                #pragma unroll
                for (int np = 0; np < 2; np++) {
                    MMA_F16(acc[mt][2 * np],     a[mt][0], a[mt][1], a[mt][2], a[mt][3],
                            b[np][0], b[np][1]);
                    MMA_F16(acc[mt][2 * np + 1], a[mt][0], a[mt][1], a[mt][2], a[mt][3],
                            b[np][2], b[np][3]);
                }
            }
        }
        if (++rs == STAGES) rs = 0;
    }

    // ---- epilogue: acc + bias -> out ----
    const int mbase = m0 + wm * 64;
    const int nbase = n0 + wn * 32;
    #pragma unroll
    for (int mt = 0; mt < 4; mt++) {
        #pragma unroll
        for (int nt = 0; nt < 4; nt++) {
            int mrow = mbase + mt * 16 + r;
            int ncol = nbase + nt * 8 + 2 * c;
            float2 bv = *reinterpret_cast<const float2*>(g_bias + ncol);
            float2 v0, v1;
            v0.x = acc[mt][nt][0] + bv.x;
            v0.y = acc[mt][nt][1] + bv.y;
            v1.x = acc[mt][nt][2] + bv.x;
            v1.y = acc[mt][nt][3] + bv.y;
            *reinterpret_cast<float2*>(out + (size_t)mrow * DIM_N + ncol) = v0;
            *reinterpret_cast<float2*>(out + (size_t)(mrow + 8) * DIM_N + ncol) = v1;
        }
    }
}

// ---------------- host launch ----------------------------------------------
extern "C" void kernel_launch(void* const* d_in, const int* in_sizes, int n_in,
                              void* d_out, int out_size) {
    const float* x = (const float*)d_in[0];
    const float* W = (const float*)d_in[1];
    float* out = (float*)d_out;

    cudaFuncSetAttribute(kan_gemm_kernel, cudaFuncAttributeMaxDynamicSharedMemorySize,
                         SMEM_BYTES);

    prep_x_kernel<<<(BATCH_M * DIM_K / 4) / 256, 256>>>(x);
    prep_w_kernel<<<(DIM_N * DIM_K) / 1024, 1024>>>(W);
    kan_gemm_kernel<<<dim3(BATCH_M / BM, DIM_N / BN), 256, SMEM_BYTES>>>(out);
}

// round 6
// speedup vs baseline: 2.6087x; 1.0564x over previous
#include <cuda_runtime.h>
#include <cuda_fp16.h>
#include <cstdint>

// ============================================================================
// UniversalKANLinear: out[b,o] = sum_k (softplus(x[b,k])-ln2) * W[o,k]
//                              + (softplus(1)-ln2) * W[o,2048]
// B=8192, K=2048, N=2048.
// sm_103 (no tcgen05/TMA). fp16 mma.sync.m16n8k16, fp32 accumulate.
// R6: single fused prep kernel (phi(x)->fp16, W->fp16, bias) to cut prep time
//     + launch overhead. GEMM: 128x128x64, 8 warps (64x32), 3-stage cp.async,
//     2 CTAs/SM (96KB smem), XOR-swizzled smem + ldmatrix.x4.
// ============================================================================

#define BATCH_M 8192
#define DIM_K   2048
#define DIM_N   2048
#define W_COLS  2049

#define BM 128
#define BN 128
#define BK 64
#define STAGES 3
#define KITERS (DIM_K / BK)     // 32

// smem: rows of 64 fp16 = 128 B, XOR-swizzled in 16B chunks
#define A_STAGE_BYTES (BM * 128)                 // 16384
#define B_STAGE_BYTES (BN * 128)                 // 16384
#define STAGE_BYTES   (A_STAGE_BYTES + B_STAGE_BYTES)  // 32768
#define SMEM_BYTES    (STAGES * STAGE_BYTES)           // 98304

#define C_BIAS 0.62011450695827751f   // softplus(1) - ln2
#define LN2F   0.69314718055994531f

#define NX_BLOCKS 16384   // x part: 16384 blocks x 256 thr x 1 float4
#define NW_BLOCKS 4096    // W part: 4096 blocks x 256 thr x 4 scalars

// ---------------- scratch (device globals: allocation-free rule) -----------
__device__ __align__(1024) __half g_A[(size_t)BATCH_M * DIM_K];  // 32 MB phi(x)
__device__ __align__(1024) __half g_B[(size_t)DIM_N * DIM_K];    // 8 MB W
__device__ __align__(128)  float  g_bias[DIM_N];

// ---------------- helpers ---------------------------------------------------
__device__ __forceinline__ uint32_t smem_u32(const void* p) {
    uint32_t a;
    asm("{ .reg .u64 t; cvta.to.shared.u64 t, %1; cvt.u32.u64 %0, t; }" : "=r"(a) : "l"(p));
    return a;
}

#define CP_ASYNC16(dst_u32, src_ptr) \
    asm volatile("cp.async.cg.shared.global [%0], [%1], 16;" \
                 :: "r"(dst_u32), "l"(src_ptr) : "memory")
#define CP_COMMIT() asm volatile("cp.async.commit_group;" ::: "memory")
#define CP_WAIT(N)  asm volatile("cp.async.wait_group %0;" :: "n"(N) : "memory")

#define LDMATRIX_X4(r0, r1, r2, r3, addr) \
    asm volatile("ldmatrix.sync.aligned.m8n8.x4.shared.b16 {%0,%1,%2,%3}, [%4];" \
                 : "=r"(r0), "=r"(r1), "=r"(r2), "=r"(r3) : "r"(addr))

#define MMA_F16(c, a0, a1, a2, a3, b0, b1) \
    asm volatile("mma.sync.aligned.m16n8k16.row.col.f32.f16.f16.f32 " \
                 "{%0,%1,%2,%3}, {%4,%5,%6,%7}, {%8,%9}, {%0,%1,%2,%3};" \
                 : "+f"((c)[0]), "+f"((c)[1]), "+f"((c)[2]), "+f"((c)[3]) \
                 : "r"(a0), "r"(a1), "r"(a2), "r"(a3), "r"(b0), "r"(b1))

// ---------------- fused pre-pass kernel -------------------------------------
__device__ __forceinline__ float phi_f(float x) {
    float t = __expf(-fabsf(x));
    return fmaxf(x, 0.0f) + __logf(1.0f + t) - LN2F;
}

__global__ void __launch_bounds__(256)
prep_fused_kernel(const float* __restrict__ x, const float* __restrict__ W) {
    const int b = blockIdx.x;
    const int tid = threadIdx.x;
    if (b < NX_BLOCKS) {
        // phi(x) -> g_A (fp16), one float4 per thread
        size_t i = (size_t)b * 256 + tid;
        float4 v = reinterpret_cast<const float4*>(x)[i];
        __half2 h0 = __floats2half2_rn(phi_f(v.x), phi_f(v.y));
        __half2 h1 = __floats2half2_rn(phi_f(v.z), phi_f(v.w));
        uint2 pack;
        pack.x = *reinterpret_cast<uint32_t*>(&h0);
        pack.y = *reinterpret_cast<uint32_t*>(&h1);
        reinterpret_cast<uint2*>(g_A)[i] = pack;
    } else {
        // W repack -> g_B (fp16), 4 consecutive k per thread (same row: k%4==0
        // chunks never straddle rows since 2048 % 4 == 0)
        const int wb = b - NX_BLOCKS;
        size_t base = (size_t)wb * 1024 + tid * 4;
        int o = (int)(base >> 11);
        int k = (int)(base & 2047);
        const float* wr = W + (size_t)o * W_COLS + k;
        __half2 h0 = __floats2half2_rn(wr[0], wr[1]);
        __half2 h1 = __floats2half2_rn(wr[2], wr[3]);
        uint2 pack;
        pack.x = *reinterpret_cast<uint32_t*>(&h0);
        pack.y = *reinterpret_cast<uint32_t*>(&h1);
        *reinterpret_cast<uint2*>(g_B + base) = pack;
        if (wb == 0) {
            for (int o2 = tid; o2 < DIM_N; o2 += 256)
                g_bias[o2] = C_BIAS * W[(size_t)o2 * W_COLS + (W_COLS - 1)];
        }
    }
}

// ---------------- GEMM kernel ----------------------------------------------
// smem addr for (row, 16B-chunk c16): row*128 + (c16 ^ (row&7))*16
__global__ void __launch_bounds__(256, 2)
kan_gemm_kernel(float* __restrict__ out) {
    extern __shared__ char smem[];
    const uint32_t sbase = smem_u32(smem);
    const int tid = threadIdx.x;
    const int lane = tid & 31;
    const int wid = tid >> 5;
    const int wm = wid & 1;        // 2 warp rows over BM=128 (64 each)
    const int wn = wid >> 1;       // 4 warp cols over BN=128 (32 each)
    const int m0 = blockIdx.x * BM;
    const int n0 = blockIdx.y * BN;
    const int r = lane >> 2;       // 0..7
    const int c = lane & 3;        // 0..3

    // ---- stage copy: A tile (128 rows x 128B) + B tile (128 rows x 128B) ----
    auto copy_stage = [&](int s, int kt) {
        const uint32_t sA = sbase + (uint32_t)s * STAGE_BYTES;
        const uint32_t sB = sA + A_STAGE_BYTES;
        const __half* gA = g_A + (size_t)m0 * DIM_K + (size_t)kt * BK;
        const __half* gB = g_B + (size_t)n0 * DIM_K + (size_t)kt * BK;
        #pragma unroll
        for (int i = 0; i < 4; i++) {            // A: 1024 16B chunks
            int v = tid + i * 256;
            int row = v >> 3, c16 = v & 7;
            CP_ASYNC16(sA + row * 128 + ((c16 ^ (row & 7)) * 16),
                       gA + (size_t)row * DIM_K + c16 * 8);
        }
        #pragma unroll
        for (int i = 0; i < 4; i++) {            // B: 1024 16B chunks
            int v = tid + i * 256;
            int row = v >> 3, c16 = v & 7;
            CP_ASYNC16(sB + row * 128 + ((c16 ^ (row & 7)) * 16),
                       gB + (size_t)row * DIM_K + c16 * 8);
        }
    };

    float acc[4][4][4];
    #pragma unroll
    for (int mt = 0; mt < 4; mt++)
        #pragma unroll
        for (int nt = 0; nt < 4; nt++)
            #pragma unroll
            for (int i = 0; i < 4; i++) acc[mt][nt][i] = 0.0f;

    copy_stage(0, 0); CP_COMMIT();
    copy_stage(1, 1); CP_COMMIT();

    // ldmatrix lane roles (loop-invariant)
    const int a_row = (lane & 15);                       // row within 16-row tile
    const int a_ch  = (lane >> 4);                       // k16 half (16B chunk)
    const int b_nrow = ((lane >> 4) << 3) + (lane & 7);  // 0-7 then 8-15
    const int b_ch  = (lane >> 3) & 1;                   // k-chunk within k16

    int rs = 0;  // read stage
    for (int kt = 0; kt < KITERS; kt++) {
        CP_WAIT(1);
        __syncthreads();
        if (kt + 2 < KITERS) copy_stage((kt + 2) % STAGES, kt + 2);
        CP_COMMIT();

        const uint32_t sA = sbase + (uint32_t)rs * STAGE_BYTES + (wm * 64) * 128;
        const uint32_t sB = sbase + (uint32_t)rs * STAGE_BYTES + A_STAGE_BYTES
                            + (wn * 32) * 128;

        #pragma unroll
        for (int ks = 0; ks < 4; ks++) {        // 4 x k16 steps over BK=64
            uint32_t a[4][4], b[2][4];
            #pragma unroll
            for (int mt = 0; mt < 4; mt++) {
                int row = mt * 16 + a_row;
                int ch = ks * 2 + a_ch;
                uint32_t addr = sA + row * 128 + ((ch ^ (row & 7)) * 16);
                LDMATRIX_X4(a[mt][0], a[mt][1], a[mt][2], a[mt][3], addr);
            }
            #pragma unroll
            for (int np = 0; np < 2; np++) {    // 2 x 16 n-rows = 32 cols
                int row = np * 16 + b_nrow;
                int ch = ks * 2 + b_ch;
                uint32_t addr = sB + row * 128 + ((ch ^ (row & 7)) * 16);
                LDMATRIX_X4(b[np][0], b[np][1], b[np][2], b[np][3], addr);
            }
            #pragma unroll
            for (int mt = 0; mt < 4; mt++) {
                #pragma unroll
                for (int np = 0; np < 2; np++) {
                    MMA_F16(acc[mt][2 * np],     a[mt][0], a[mt][1], a[mt][2], a[mt][3],
                            b[np][0], b[np][1]);
                    MMA_F16(acc[mt][2 * np + 1], a[mt][0], a[mt][1], a[mt][2], a[mt][3],
                            b[np][2], b[np][3]);
                }
            }
        }
        if (++rs == STAGES) rs = 0;
    }

    // ---- epilogue: acc + bias -> out ----
    const int mbase = m0 + wm * 64;
    const int nbase = n0 + wn * 32;
    #pragma unroll
    for (int mt = 0; mt < 4; mt++) {
        #pragma unroll
        for (int nt = 0; nt < 4; nt++) {
            int mrow = mbase + mt * 16 + r;
            int ncol = nbase + nt * 8 + 2 * c;
            float2 bv = *reinterpret_cast<const float2*>(g_bias + ncol);
            float2 v0, v1;
            v0.x = acc[mt][nt][0] + bv.x;
            v0.y = acc[mt][nt][1] + bv.y;
            v1.x = acc[mt][nt][2] + bv.x;
            v1.y = acc[mt][nt][3] + bv.y;
            *reinterpret_cast<float2*>(out + (size_t)mrow * DIM_N + ncol) = v0;
            *reinterpret_cast<float2*>(out + (size_t)(mrow + 8) * DIM_N + ncol) = v1;
        }
    }
}

// ---------------- host launch ----------------------------------------------
extern "C" void kernel_launch(void* const* d_in, const int* in_sizes, int n_in,
                              void* d_out, int out_size) {
    const float* x = (const float*)d_in[0];
    const float* W = (const float*)d_in[1];
    float* out = (float*)d_out;

    cudaFuncSetAttribute(kan_gemm_kernel, cudaFuncAttributeMaxDynamicSharedMemorySize,
                         SMEM_BYTES);

    prep_fused_kernel<<<NX_BLOCKS + NW_BLOCKS, 256>>>(x, W);
    kan_gemm_kernel<<<dim3(BATCH_M / BM, DIM_N / BN), 256, SMEM_BYTES>>>(out);
}

// round 7
// speedup vs baseline: 2.6294x; 1.0079x over previous
#include <cuda_runtime.h>
#include <cuda_fp16.h>
#include <cstdint>

// ============================================================================
// UniversalKANLinear: out[b,o] = sum_k (softplus(x[b,k])-ln2) * W[o,k]
//                              + (softplus(1)-ln2) * W[o,2048]
// B=8192, K=2048, N=2048.
// sm_103 (no tcgen05/TMA). fp16 mma.sync.m16n8k16, fp32 accumulate.
// R7: tail-only split-K. Grid 888 full tiles (3 waves @ 296 slots) + last 136
//     tiles split K/2 into 272 half-units (1 final wave) => ~3.5 waves vs 4.
//     Split tiles accumulate via RED.ADD.F32 into a pre-zeroed out region
//     (exactly 2 commutative contributions per element -> deterministic).
// ============================================================================

#define BATCH_M 8192
#define DIM_K   2048
#define DIM_N   2048
#define W_COLS  2049

#define BM 128
#define BN 128
#define BK 64
#define KITERS (DIM_K / BK)     // 32
#define STAGES 3

#define MTILES (BATCH_M / BM)   // 64
#define NTILES (DIM_N / BN)     // 16
#define NTILES_TOTAL (MTILES * NTILES)   // 1024
#define FULL_TILES 888
#define SPLIT_TILES (NTILES_TOTAL - FULL_TILES)  // 136
#define GRID_GEMM (FULL_TILES + 2 * SPLIT_TILES) // 1160
#define KHALF (KITERS / 2)      // 16

// smem: rows of 64 fp16 = 128 B, XOR-swizzled in 16B chunks
#define A_STAGE_BYTES (BM * 128)                 // 16384
#define B_STAGE_BYTES (BN * 128)                 // 16384
#define STAGE_BYTES   (A_STAGE_BYTES + B_STAGE_BYTES)  // 32768
#define SMEM_BYTES    (STAGES * STAGE_BYTES)           // 98304

#define C_BIAS 0.62011450695827751f   // softplus(1) - ln2
#define LN2F   0.69314718055994531f

// prep grid layout
#define NX_BLOCKS 8192    // x: 8192 blocks x 256 thr x 2 float4
#define NW_BLOCKS 4096    // W: 4096 blocks x 256 thr x 4 scalars
#define NZ_BLOCKS (SPLIT_TILES * 16)  // zero: 16 blocks/tile x 256 thr x float4

// ---------------- scratch (device globals: allocation-free rule) -----------
__device__ __align__(1024) __half g_A[(size_t)BATCH_M * DIM_K];  // 32 MB phi(x)
__device__ __align__(1024) __half g_B[(size_t)DIM_N * DIM_K];    // 8 MB W
__device__ __align__(128)  float  g_bias[DIM_N];

// ---------------- helpers ---------------------------------------------------
__device__ __forceinline__ uint32_t smem_u32(const void* p) {
    uint32_t a;
    asm("{ .reg .u64 t; cvta.to.shared.u64 t, %1; cvt.u32.u64 %0, t; }" : "=r"(a) : "l"(p));
    return a;
}

#define CP_ASYNC16(dst_u32, src_ptr) \
    asm volatile("cp.async.cg.shared.global [%0], [%1], 16;" \
                 :: "r"(dst_u32), "l"(src_ptr) : "memory")
#define CP_COMMIT() asm volatile("cp.async.commit_group;" ::: "memory")
#define CP_WAIT(N)  asm volatile("cp.async.wait_group %0;" :: "n"(N) : "memory")

#define LDMATRIX_X4(r0, r1, r2, r3, addr) \
    asm volatile("ldmatrix.sync.aligned.m8n8.x4.shared.b16 {%0,%1,%2,%3}, [%4];" \
                 : "=r"(r0), "=r"(r1), "=r"(r2), "=r"(r3) : "r"(addr))

#define MMA_F16(c, a0, a1, a2, a3, b0, b1) \
    asm volatile("mma.sync.aligned.m16n8k16.row.col.f32.f16.f16.f32 " \
                 "{%0,%1,%2,%3}, {%4,%5,%6,%7}, {%8,%9}, {%0,%1,%2,%3};" \
                 : "+f"((c)[0]), "+f"((c)[1]), "+f"((c)[2]), "+f"((c)[3]) \
                 : "r"(a0), "r"(a1), "r"(a2), "r"(a3), "r"(b0), "r"(b1))

// ---------------- fused pre-pass kernel -------------------------------------
__device__ __forceinline__ float phi_f(float x) {
    float t = __expf(-fabsf(x));
    return fmaxf(x, 0.0f) + __logf(1.0f + t) - LN2F;
}

__device__ __forceinline__ uint2 phi_pack(float4 v) {
    __half2 h0 = __floats2half2_rn(phi_f(v.x), phi_f(v.y));
    __half2 h1 = __floats2half2_rn(phi_f(v.z), phi_f(v.w));
    uint2 p;
    p.x = *reinterpret_cast<uint32_t*>(&h0);
    p.y = *reinterpret_cast<uint32_t*>(&h1);
    return p;
}

__global__ void __launch_bounds__(256)
prep_fused_kernel(const float* __restrict__ x, const float* __restrict__ W,
                  float* __restrict__ out) {
    const int b = blockIdx.x;
    const int tid = threadIdx.x;
    if (b < NX_BLOCKS) {
        // phi(x) -> g_A (fp16), two float4 per thread
        size_t i = (size_t)b * 512 + tid;
        float4 v0 = reinterpret_cast<const float4*>(x)[i];
        float4 v1 = reinterpret_cast<const float4*>(x)[i + 256];
        reinterpret_cast<uint2*>(g_A)[i]       = phi_pack(v0);
        reinterpret_cast<uint2*>(g_A)[i + 256] = phi_pack(v1);
    } else if (b < NX_BLOCKS + NW_BLOCKS) {
        // W repack -> g_B (fp16), 4 consecutive k per thread
        const int wb = b - NX_BLOCKS;
        size_t base = (size_t)wb * 1024 + tid * 4;
        int o = (int)(base >> 11);
        int k = (int)(base & 2047);
        const float* wr = W + (size_t)o * W_COLS + k;
        __half2 h0 = __floats2half2_rn(wr[0], wr[1]);
        __half2 h1 = __floats2half2_rn(wr[2], wr[3]);
        uint2 pack;
        pack.x = *reinterpret_cast<uint32_t*>(&h0);
        pack.y = *reinterpret_cast<uint32_t*>(&h1);
        *reinterpret_cast<uint2*>(g_B + base) = pack;
        if (wb == 0) {
            for (int o2 = tid; o2 < DIM_N; o2 += 256)
                g_bias[o2] = C_BIAS * W[(size_t)o2 * W_COLS + (W_COLS - 1)];
        }
    } else {
        // zero the out regions of the split tiles (tiles FULL_TILES..1023)
        const int zb = b - (NX_BLOCKS + NW_BLOCKS);
        const int t = FULL_TILES + (zb >> 4);      // 16 blocks per tile
        const int mx = t % MTILES, ny = t / MTILES;
        const int inner = ((zb & 15) << 8) + tid;  // 0..4095 float4s
        const int row = inner >> 5;                // 32 float4s per 128-col row
        const int col = inner & 31;
        float4 z = {0.f, 0.f, 0.f, 0.f};
        *reinterpret_cast<float4*>(out + (size_t)(mx * BM + row) * DIM_N
                                   + ny * BN + col * 4) = z;
    }
}

// ---------------- GEMM kernel ----------------------------------------------
// smem addr for (row, 16B-chunk c16): row*128 + (c16 ^ (row&7))*16
__global__ void __launch_bounds__(256, 2)
kan_gemm_kernel(float* __restrict__ out) {
    extern __shared__ char smem[];
    const uint32_t sbase = smem_u32(smem);
    const int tid = threadIdx.x;
    const int lane = tid & 31;
    const int wid = tid >> 5;
    const int wm = wid & 1;        // 2 warp rows over BM=128 (64 each)
    const int wn = wid >> 1;       // 4 warp cols over BN=128 (32 each)
    const int r = lane >> 2;       // 0..7
    const int c = lane & 3;        // 0..3

    // ---- tile scheduling: full tiles, then split-K halves of the tail ----
    const int bid = blockIdx.x;
    int tile, k0, kn;
    bool split;
    int khalf = 0;
    if (bid < FULL_TILES) {
        tile = bid; k0 = 0; kn = KITERS; split = false;
    } else {
        int u = bid - FULL_TILES;           // 0..271
        tile = FULL_TILES + (u % SPLIT_TILES);
        khalf = u / SPLIT_TILES;            // 0 or 1
        k0 = khalf * KHALF; kn = KHALF; split = true;
    }
    const int m0 = (tile % MTILES) * BM;
    const int n0 = (tile / MTILES) * BN;

    // ---- stage copy: A tile (128 rows x 128B) + B tile (128 rows x 128B) ----
    auto copy_stage = [&](int s, int kt) {
        const uint32_t sA = sbase + (uint32_t)s * STAGE_BYTES;
        const uint32_t sB = sA + A_STAGE_BYTES;
        const __half* gA = g_A + (size_t)m0 * DIM_K + (size_t)kt * BK;
        const __half* gB = g_B + (size_t)n0 * DIM_K + (size_t)kt * BK;
        #pragma unroll
        for (int i = 0; i < 4; i++) {            // A: 1024 16B chunks
            int v = tid + i * 256;
            int row = v >> 3, c16 = v & 7;
            CP_ASYNC16(sA + row * 128 + ((c16 ^ (row & 7)) * 16),
                       gA + (size_t)row * DIM_K + c16 * 8);
        }
        #pragma unroll
        for (int i = 0; i < 4; i++) {            // B: 1024 16B chunks
            int v = tid + i * 256;
            int row = v >> 3, c16 = v & 7;
            CP_ASYNC16(sB + row * 128 + ((c16 ^ (row & 7)) * 16),
                       gB + (size_t)row * DIM_K + c16 * 8);
        }
    };

    float acc[4][4][4];
    #pragma unroll
    for (int mt = 0; mt < 4; mt++)
        #pragma unroll
        for (int nt = 0; nt < 4; nt++)
            #pragma unroll
            for (int i = 0; i < 4; i++) acc[mt][nt][i] = 0.0f;

    copy_stage(0, k0); CP_COMMIT();
    copy_stage(1, k0 + 1); CP_COMMIT();

    // ldmatrix lane roles (loop-invariant)
    const int a_row = (lane & 15);                       // row within 16-row tile
    const int a_ch  = (lane >> 4);                       // k16 half (16B chunk)
    const int b_nrow = ((lane >> 4) << 3) + (lane & 7);  // 0-7 then 8-15
    const int b_ch  = (lane >> 3) & 1;                   // k-chunk within k16

    int rs = 0;  // read stage
    for (int kt = 0; kt < kn; kt++) {
        CP_WAIT(1);
        __syncthreads();
        if (kt + 2 < kn) copy_stage((kt + 2) % STAGES, k0 + kt + 2);
        CP_COMMIT();

        const uint32_t sA = sbase + (uint32_t)rs * STAGE_BYTES + (wm * 64) * 128;
        const uint32_t sB = sbase + (uint32_t)rs * STAGE_BYTES + A_STAGE_BYTES
                            + (wn * 32) * 128;

        #pragma unroll
        for (int ks = 0; ks < 4; ks++) {        // 4 x k16 steps over BK=64
            uint32_t a[4][4], b[2][4];
            #pragma unroll
            for (int mt = 0; mt < 4; mt++) {
                int row = mt * 16 + a_row;
                int ch = ks * 2 + a_ch;
                uint32_t addr = sA + row * 128 + ((ch ^ (row & 7)) * 16);
                LDMATRIX_X4(a[mt][0], a[mt][1], a[mt][2], a[mt][3], addr);
            }
            #pragma unroll
            for (int np = 0; np < 2; np++) {    // 2 x 16 n-rows = 32 cols
                int row = np * 16 + b_nrow;
                int ch = ks * 2 + b_ch;
                uint32_t addr = sB + row * 128 + ((ch ^ (row & 7)) * 16);
                LDMATRIX_X4(b[np][0], b[np][1], b[np][2], b[np][3], addr);
            }
            #pragma unroll
            for (int mt = 0; mt < 4; mt++) {
                #pragma unroll
                for (int np = 0; np < 2; np++) {
                    MMA_F16(acc[mt][2 * np],     a[mt][0], a[mt][1], a[mt][2], a[mt][3],
                            b[np][0], b[np][1]);
                    MMA_F16(acc[mt][2 * np + 1], a[mt][0], a[mt][1], a[mt][2], a[mt][3],
                            b[np][2], b[np][3]);
                }
            }
        }
        if (++rs == STAGES) rs = 0;
    }

    // ---- epilogue ----
    const int mbase = m0 + wm * 64;
    const int nbase = n0 + wn * 32;
    const bool addb = !split || (khalf == 0);   // bias added exactly once
    #pragma unroll
    for (int mt = 0; mt < 4; mt++) {
        #pragma unroll
        for (int nt = 0; nt < 4; nt++) {
            int mrow = mbase + mt * 16 + r;
            int ncol = nbase + nt * 8 + 2 * c;
            float2 bv = *reinterpret_cast<const float2*>(g_bias + ncol);
            float v0x = acc[mt][nt][0] + (addb ? bv.x : 0.0f);
            float v0y = acc[mt][nt][1] + (addb ? bv.y : 0.0f);
            float v1x = acc[mt][nt][2] + (addb ? bv.x : 0.0f);
            float v1y = acc[mt][nt][3] + (addb ? bv.y : 0.0f);
            float* p0 = out + (size_t)mrow * DIM_N + ncol;
            float* p1 = out + (size_t)(mrow + 8) * DIM_N + ncol;
            if (!split) {
                *reinterpret_cast<float2*>(p0) = make_float2(v0x, v0y);
                *reinterpret_cast<float2*>(p1) = make_float2(v1x, v1y);
            } else {
                atomicAdd(p0, v0x);
                atomicAdd(p0 + 1, v0y);
                atomicAdd(p1, v1x);
                atomicAdd(p1 + 1, v1y);
            }
        }
    }
}

// ---------------- host launch ----------------------------------------------
extern "C" void kernel_launch(void* const* d_in, const int* in_sizes, int n_in,
                              void* d_out, int out_size) {
    const float* x = (const float*)d_in[0];
    const float* W = (const float*)d_in[1];
    float* out = (float*)d_out;

    cudaFuncSetAttribute(kan_gemm_kernel, cudaFuncAttributeMaxDynamicSharedMemorySize,
                         SMEM_BYTES);

    prep_fused_kernel<<<NX_BLOCKS + NW_BLOCKS + NZ_BLOCKS, 256>>>(x, W, out);
    kan_gemm_kernel<<<GRID_GEMM, 256, SMEM_BYTES>>>(out);
}